// round 12
// baseline (speedup 1.0000x reference)
#include <cuda_runtime.h>
#include <cuda_bf16.h>
#include <cuda_fp16.h>
#include <math.h>
#include <stdint.h>

#define Q_LEN 2048
#define K_LEN 2048
#define BATCH 4
#define HEADS 8
#define EMB 512
#define INP 544
#define HD 32
#define BHN (BATCH*HEADS)

// projected q/k, bf16 hi/lo split, layout [bh][seq][32]
__device__ __nv_bfloat16 g_qh[(size_t)BHN * Q_LEN * HD];
__device__ __nv_bfloat16 g_ql[(size_t)BHN * Q_LEN * HD];
__device__ __nv_bfloat16 g_kh[(size_t)BHN * K_LEN * HD];
__device__ __nv_bfloat16 g_kl[(size_t)BHN * K_LEN * HD];
__device__ float g_pe[(size_t)Q_LEN * EMB];
__device__ int g_dummy;

// ─────────────────── profiler-alignment dummy (launch #0) ───────────────────
__global__ void warm_kernel() { g_dummy = 1; }

// ───────────────────────── PE table ─────────────────────────
__global__ void pe_kernel() {
    int idx = blockIdx.x * 256 + threadIdx.x;
    int pos = idx >> 8;
    int i2  = idx & 255;
    float e = 2.0f * (float)i2;
    float div = expf(e * (-9.210340371976184f / 512.0f));
    float a = (float)pos * div;
    g_pe[(size_t)pos * EMB + 2 * i2]     = sinf(a);
    g_pe[(size_t)pos * EMB + 2 * i2 + 1] = cosf(a);
}

// ───────────────────────── projection (fp32, bf16 hi/lo out) ─────────────────────────
__global__ void __launch_bounds__(256, 2) proj_kernel(
        const float* __restrict__ qin, const float* __restrict__ kin,
        const float* __restrict__ Wq,  const float* __restrict__ bq,
        const float* __restrict__ Wk,  const float* __restrict__ bk) {
    __shared__ float As[32 * 36];
    __shared__ float Bs[32 * 256];

    const int is_q = (blockIdx.z == 0);
    const float* in   = is_q ? qin : kin;
    const float* W    = is_q ? Wq  : Wk;
    const float* bias = is_q ? bq  : bk;
    const int off     = is_q ? 0 : 256;
    __nv_bfloat16* oh = is_q ? g_qh : g_kh;
    __nv_bfloat16* ol = is_q ? g_ql : g_kl;

    int b  = blockIdx.y;
    int q0 = blockIdx.x * 32;
    int col = threadIdx.x;

    float acc[32];
    float bv = bias[off + col];
#pragma unroll
    for (int r = 0; r < 32; r++) acc[r] = bv;

    for (int et = 0; et < 16; et++) {
        {
            int i = threadIdx.x;
#pragma unroll
            for (int j = 0; j < 4; j++, i += 256) {
                int r = i >> 5, e = i & 31;
                int ge = et * 32 + e;
                float v = in[((size_t)(q0 + r) * BATCH + b) * EMB + ge];
                if (is_q) v += g_pe[(size_t)(q0 + r) * EMB + ge];
                As[r * 36 + e] = v;
            }
        }
#pragma unroll
        for (int e = 0; e < 32; e++)
            Bs[e * 256 + col] = W[(size_t)(et * 32 + e) * INP + off + col];
        __syncthreads();

#pragma unroll
        for (int e4 = 0; e4 < 8; e4++) {
            float b0 = Bs[(e4 * 4 + 0) * 256 + col];
            float b1 = Bs[(e4 * 4 + 1) * 256 + col];
            float b2 = Bs[(e4 * 4 + 2) * 256 + col];
            float b3 = Bs[(e4 * 4 + 3) * 256 + col];
#pragma unroll
            for (int r = 0; r < 32; r++) {
                float4 a4 = *(const float4*)&As[r * 36 + e4 * 4];
                acc[r] += a4.x * b0;
                acc[r] += a4.y * b1;
                acc[r] += a4.z * b2;
                acc[r] += a4.w * b3;
            }
        }
        __syncthreads();
    }

    int h = col >> 5, d = col & 31;
#pragma unroll
    for (int r = 0; r < 32; r++) {
        float v = acc[r];
        __nv_bfloat16 hi = __float2bfloat16(v);
        __nv_bfloat16 lo = __float2bfloat16(v - __bfloat162float(hi));
        size_t idx = ((size_t)(b * HEADS + h) * Q_LEN + (q0 + r)) * HD + d;
        oh[idx] = hi;
        ol[idx] = lo;
    }
}

// ───────────────────────── attention (single-pass HMMA) ─────────────────────────
__device__ __forceinline__ void mma_bf16(float& d0, float& d1, float& d2, float& d3,
                                         const uint32_t a[4], const uint32_t b[2]) {
    asm volatile(
        "mma.sync.aligned.m16n8k16.row.col.f32.bf16.bf16.f32 "
        "{%0,%1,%2,%3}, {%4,%5,%6,%7}, {%8,%9}, {%0,%1,%2,%3};\n"
        : "+f"(d0), "+f"(d1), "+f"(d2), "+f"(d3)
        : "r"(a[0]), "r"(a[1]), "r"(a[2]), "r"(a[3]), "r"(b[0]), "r"(b[1]));
}

// smem layout (bytes):
//   kpm    [0, 2048)
//   sums   [2048, 3072)      32 rows x 8 slices
//   rinv   [3072, 3200)
//   qh/ql  [3200, 8320)      32 x 40 bf16 each   (dead after frag load)
//   am     [8320, 74368)     32 rows x 2064 pitch (dead after mainloop)
//   stage  [3200, 138368)    8 warps x 16 x 264 f32 (aliases q + am, used after)
#define OFF_KPM   0
#define OFF_SUMS  2048
#define OFF_RINV  3072
#define OFF_Q     3200
#define OFF_AM    8320
#define OFF_STAGE 3200
#define SMEM_ATTN 138368
#define AMP 2064        // am row pitch (16B aligned, bank-skewed)
#define STP 264         // stage row pitch in f32

__global__ void __launch_bounds__(512, 1) attn_kernel(
        const unsigned char* __restrict__ am,
        const unsigned char* __restrict__ kpm,
        float* __restrict__ out) {
    extern __shared__ char smem[];
    unsigned char* kpm_s = (unsigned char*)(smem + OFF_KPM);
    float* sums_s = (float*)(smem + OFF_SUMS);
    float* rinv_s = (float*)(smem + OFF_RINV);
    __nv_bfloat16* qh_s = (__nv_bfloat16*)(smem + OFF_Q);
    __nv_bfloat16* ql_s = qh_s + 32 * 40;
    unsigned char* am_s = (unsigned char*)(smem + OFF_AM);
    float* stage = (float*)(smem + OFF_STAGE);

    int tid = threadIdx.x, w = tid >> 5, lane = tid & 31;
    int g = lane >> 2, qr = lane & 3;
    int rh = w & 1, cs = w >> 1;           // row-half / col-slice(256)
    int bh = blockIdx.y, b = bh >> 3, h = bh & 7;
    int q0 = blockIdx.x * 32;
    int colbase = cs * 256;

    // load q hi/lo tiles (32 rows x 32 = 128 uint4 each)
    if (tid < 128) {
        int r = tid >> 2, c = tid & 3;
        *(uint4*)(qh_s + r * 40 + c * 8) =
            ((const uint4*)g_qh)[((size_t)bh * Q_LEN + q0 + r) * 4 + c];
        ((uint4*)kpm_s)[tid] = ((const uint4*)(kpm + (size_t)b * K_LEN))[tid];
    } else if (tid < 256) {
        int i = tid - 128;
        int r = i >> 2, c = i & 3;
        *(uint4*)(ql_s + r * 40 + c * 8) =
            ((const uint4*)g_ql)[((size_t)bh * Q_LEN + q0 + r) * 4 + c];
    }
    // am slice: 32 rows x 2048 B -> padded smem
    {
        int r = tid >> 4, sg = tid & 15;
        const uint4* src = (const uint4*)(am + (size_t)(q0 + r) * K_LEN + sg * 128);
        uint4* dst = (uint4*)(am_s + r * AMP + sg * 128);
#pragma unroll
        for (int j = 0; j < 8; j++) dst[j] = src[j];
    }
    __syncthreads();

    // A fragments (held whole kernel)
    const uint32_t* qh32 = (const uint32_t*)qh_s;
    const uint32_t* ql32 = (const uint32_t*)ql_s;
    int R1 = rh * 16 + g, R2 = R1 + 8;     // local rows
    uint32_t aH[2][4], aL[2][4];
#pragma unroll
    for (int kc = 0; kc < 2; kc++) {
        int c = kc * 8 + qr;
        aH[kc][0] = qh32[R1 * 20 + c];     aH[kc][1] = qh32[R2 * 20 + c];
        aH[kc][2] = qh32[R1 * 20 + c + 4]; aH[kc][3] = qh32[R2 * 20 + c + 4];
        aL[kc][0] = ql32[R1 * 20 + c];     aL[kc][1] = ql32[R2 * 20 + c];
        aL[kc][2] = ql32[R1 * 20 + c + 4]; aL[kc][3] = ql32[R2 * 20 + c + 4];
    }

    const uint32_t* kh32 = (const uint32_t*)g_kh + (size_t)bh * K_LEN * 16;
    const uint32_t* kl32 = (const uint32_t*)g_kl + (size_t)bh * K_LEN * 16;

    uint32_t p[64];          // 64 f16x2 probs (even: row R1, odd: row R2)
    float s1 = 0.f, s2 = 0.f;

#pragma unroll
    for (int nf = 0; nf < 32; nf++) {
        int n0 = colbase + nf * 8;
        int krow = (n0 + g) * 16;
        uint32_t bH[2][2], bL[2][2];
#pragma unroll
        for (int kc = 0; kc < 2; kc++) {
            bH[kc][0] = kh32[krow + kc * 8 + qr];
            bH[kc][1] = kh32[krow + kc * 8 + qr + 4];
            bL[kc][0] = kl32[krow + kc * 8 + qr];
            bL[kc][1] = kl32[krow + kc * 8 + qr + 4];
        }
        float d0 = 0.f, d1 = 0.f, d2 = 0.f, d3 = 0.f;
#pragma unroll
        for (int kc = 0; kc < 2; kc++) {
            mma_bf16(d0, d1, d2, d3, aH[kc], bH[kc]);
            mma_bf16(d0, d1, d2, d3, aH[kc], bL[kc]);
            mma_bf16(d0, d1, d2, d3, aL[kc], bH[kc]);
        }
        int col = n0 + qr * 2;
        uchar2 pm = *(const uchar2*)(kpm_s + col);
        uchar2 m1 = *(const uchar2*)(am_s + R1 * AMP + col);
        uchar2 m2 = *(const uchar2*)(am_s + R2 * AMP + col);
        float e0 = (m1.x | pm.x) ? 0.f : __expf(d0);
        float e1 = (m1.y | pm.y) ? 0.f : __expf(d1);
        float e2 = (m2.x | pm.x) ? 0.f : __expf(d2);
        float e3 = (m2.y | pm.y) ? 0.f : __expf(d3);
        s1 += e0 + e1;
        s2 += e2 + e3;
        half2 h1 = __floats2half2_rn(e0, e1);
        half2 h2 = __floats2half2_rn(e2, e3);
        p[2 * nf]     = *(uint32_t*)&h1;
        p[2 * nf + 1] = *(uint32_t*)&h2;
    }

    // row sums: quad shuffle (cols within slab), then cross-slice via smem
    s1 += __shfl_xor_sync(0xffffffffu, s1, 1);
    s1 += __shfl_xor_sync(0xffffffffu, s1, 2);
    s2 += __shfl_xor_sync(0xffffffffu, s2, 1);
    s2 += __shfl_xor_sync(0xffffffffu, s2, 2);
    if (qr == 0) {
        sums_s[R1 * 8 + cs] = s1;
        sums_s[R2 * 8 + cs] = s2;
    }
    __syncthreads();
    if (tid < 32) {
        const float* sp = &sums_s[tid * 8];
        float v = ((sp[0] + sp[1]) + (sp[2] + sp[3])) +
                  ((sp[4] + sp[5]) + (sp[6] + sp[7]));
        rinv_s[tid] = 1.0f / v;
    }
    __syncthreads();
    float riv1 = rinv_s[R1];
    float riv2 = rinv_s[R2];

    // flush: phase by row-half; 8 warps stage 16x256 f32 each, then coalesced STG
    float* mystage = stage + cs * (16 * STP);
#pragma unroll
    for (int phase = 0; phase < 2; phase++) {
        if (rh == phase) {
#pragma unroll
            for (int nf = 0; nf < 32; nf++) {
                int cl = nf * 8 + qr * 2;
                float2 v1 = __half22float2(*(half2*)&p[2 * nf]);
                float2 v2 = __half22float2(*(half2*)&p[2 * nf + 1]);
                v1.x *= riv1; v1.y *= riv1;
                v2.x *= riv2; v2.y *= riv2;
                *(float2*)&mystage[g * STP + cl] = v1;
                *(float2*)&mystage[(g + 8) * STP + cl] = v2;
            }
            __syncwarp();
#pragma unroll
            for (int rr = 0; rr < 16; rr++) {
                int grow = q0 + rh * 16 + rr;
                float4 w0 = *(const float4*)&mystage[rr * STP + lane * 4];
                float4 w1 = *(const float4*)&mystage[rr * STP + 128 + lane * 4];
                float* op = out + ((size_t)(h * BATCH + b) * Q_LEN + grow) * K_LEN + colbase;
                *(float4*)(op + lane * 4) = w0;
                *(float4*)(op + 128 + lane * 4) = w1;
            }
        }
        __syncthreads();
    }
}

extern "C" void kernel_launch(void* const* d_in, const int* in_sizes, int n_in,
                              void* d_out, int out_size) {
    const float* query = (const float*)d_in[0];
    const float* key   = (const float*)d_in[1];
    const float* Wq    = (const float*)d_in[2];
    const float* bq    = (const float*)d_in[3];
    const float* Wk    = (const float*)d_in[4];
    const float* bk    = (const float*)d_in[5];
    const unsigned char* kpm = (const unsigned char*)d_in[6];
    const unsigned char* amk = (const unsigned char*)d_in[7];
    float* out = (float*)d_out;

    cudaFuncSetAttribute(attn_kernel, cudaFuncAttributeMaxDynamicSharedMemorySize, SMEM_ATTN);

    warm_kernel<<<1, 1>>>();   // keeps attn_kernel in the ncu capture window
    pe_kernel<<<2048, 256>>>();
    proj_kernel<<<dim3(Q_LEN / 32, BATCH, 2), 256>>>(query, key, Wq, bq, Wk, bk);
    attn_kernel<<<dim3(Q_LEN / 32, BHN), 512, SMEM_ATTN>>>(amk, kpm, out);
}